// round 5
// baseline (speedup 1.0000x reference)
#include <cuda_runtime.h>
#include <math.h>

#define TT 2048
#define NROWS 128
#define NF 20
#define LK 769
#define PADL 384
#define SIGP_LEN 2816   /* TT + 2*384 */
#define NBINS 18
#define PI_F 3.14159265358979f

// -------------------- scratch (no allocs allowed) --------------------
__device__ float g_sigp[NROWS * SIGP_LEN];            // 1.44 MB
__device__ float g_filt[NROWS * NF * TT];             // 21 MB
__device__ unsigned char g_bin[NROWS * 10 * TT];      // 2.6 MB
__device__ float g_amp[NROWS * 10 * TT];              // 10.5 MB
__device__ int   g_cnt[NROWS * 10 * NBINS];

// -------------------- 1) reflect pad (effective pad 384/side) --------------------
__global__ void pad_kernel(const float* __restrict__ x) {
    int row = blockIdx.x;
    const float* xr = x + row * TT;
    float* o = g_sigp + row * SIGP_LEN;
    for (int j = threadIdx.x; j < SIGP_LEN; j += blockDim.x) {
        int i = j - PADL;
        int src = (i < 0) ? -i : ((i >= TT) ? (2 * TT - 2 - i) : i);
        o[j] = xr[src];
    }
}

// -------------------- 2) FIR conv, nonzero-trimmed, sliding register window ----
__global__ __launch_bounds__(256) void conv_kernel(const float* __restrict__ Kf) {
    __shared__ __align__(16) float ssig[2832];
    __shared__ __align__(16) float sk[784];
    __shared__ int s_lo, s_hi;
    int f = blockIdx.x, row = blockIdx.y;
    int tid = threadIdx.x;

    for (int j = tid; j < 2832; j += 256)
        ssig[j] = (j < SIGP_LEN) ? g_sigp[row * SIGP_LEN + j] : 0.f;
    for (int j = tid; j < 784; j += 256)
        sk[j] = (j < LK) ? Kf[f * LK + j] : 0.f;
    if (tid == 0) { s_lo = LK; s_hi = 0; }
    __syncthreads();

    int llo = LK, lhi = 0;
    for (int j = tid; j < LK; j += 256)
        if (sk[j] != 0.f) { if (j < llo) llo = j; if (j > lhi) lhi = j; }
    atomicMin(&s_lo, llo);
    atomicMax(&s_hi, lhi);
    __syncthreads();

    int l0 = s_lo & ~7;
    int l1 = (s_hi + 8) & ~7;     // exclusive, covers hi; zero taps are free

    int t0 = tid * 8;             // 8 consecutive outputs per thread
    float acc[8];
#pragma unroll
    for (int r = 0; r < 8; r++) acc[r] = 0.f;

    float s[16];
    {
        float4 v0 = *(const float4*)&ssig[t0 + l0];
        float4 v1 = *(const float4*)&ssig[t0 + l0 + 4];
        s[0]=v0.x; s[1]=v0.y; s[2]=v0.z; s[3]=v0.w;
        s[4]=v1.x; s[5]=v1.y; s[6]=v1.z; s[7]=v1.w;
    }
    for (int l = l0; l < l1; l += 8) {
        float4 v2 = *(const float4*)&ssig[t0 + l + 8];
        float4 v3 = *(const float4*)&ssig[t0 + l + 12];
        s[8]=v2.x;  s[9]=v2.y;  s[10]=v2.z; s[11]=v2.w;
        s[12]=v3.x; s[13]=v3.y; s[14]=v3.z; s[15]=v3.w;
#pragma unroll
        for (int j = 0; j < 8; j++) {
            float kv = sk[l + j];
#pragma unroll
            for (int r = 0; r < 8; r++) acc[r] = fmaf(s[j + r], kv, acc[r]);
        }
#pragma unroll
        for (int i = 0; i < 8; i++) s[i] = s[i + 8];
    }
    float* o = &g_filt[(row * NF + f) * TT + t0];
    *(float4*)&o[0] = make_float4(acc[0], acc[1], acc[2], acc[3]);
    *(float4*)&o[4] = make_float4(acc[4], acc[5], acc[6], acc[7]);
}

// -------------------- 3) 2048-pt radix-4 Stockham FFT + Hilbert ----------------
// Forward FFT: 5 radix-4 stages + 1 radix-2. 512 threads, 1 r4 butterfly each.
// Result ends in bufA. Inverse realized as conj -> forward -> conj / N.
__device__ __forceinline__ void fft2048_fwd(
    float* Ar, float* Ai, float* Br, float* Bi,
    const float* __restrict__ twr, const float* __restrict__ twi, int tid)
{
    float *sr = Ar, *si = Ai, *dr = Br, *di = Bi;
    int s = 1;
#pragma unroll
    for (int st = 0; st < 5; st++) {
        int b = tid;
        int k1 = b & ~(s - 1);          // p*s < 512
        int bb = b + 3 * k1;            // dst base
        float w1r = twr[k1], w1i = twi[k1];
        float w2r = w1r * w1r - w1i * w1i, w2i = 2.f * w1r * w1i;
        float w3r = w2r * w1r - w2i * w1i, w3i = w2r * w1i + w2i * w1r;

        float ar = sr[b],        ai = si[b];
        float br_ = sr[b + 512], bi_ = si[b + 512];
        float cr = sr[b + 1024], ci = si[b + 1024];
        float er = sr[b + 1536], ei = si[b + 1536];

        float apc_r = ar + cr,  apc_i = ai + ci;
        float amc_r = ar - cr,  amc_i = ai - ci;
        float bpd_r = br_ + er, bpd_i = bi_ + ei;
        float bmd_r = br_ - er, bmd_i = bi_ - ei;

        dr[bb] = apc_r + bpd_r;  di[bb] = apc_i + bpd_i;
        float y1r = amc_r + bmd_i, y1i = amc_i - bmd_r;           // amc - i*bmd
        dr[bb + s]     = y1r * w1r - y1i * w1i;  di[bb + s]     = y1r * w1i + y1i * w1r;
        float y2r = apc_r - bpd_r, y2i = apc_i - bpd_i;
        dr[bb + 2 * s] = y2r * w2r - y2i * w2i;  di[bb + 2 * s] = y2r * w2i + y2i * w2r;
        float y3r = amc_r - bmd_i, y3i = amc_i + bmd_r;           // amc + i*bmd
        dr[bb + 3 * s] = y3r * w3r - y3i * w3i;  di[bb + 3 * s] = y3r * w3i + y3i * w3r;
        __syncthreads();
        float* t;
        t = sr; sr = dr; dr = t;
        t = si; si = di; di = t;
        s <<= 2;
    }
    // radix-2 final stage (twiddle = 1); reads sr(=B), writes dr(=A)
#pragma unroll
    for (int u = 0; u < 2; u++) {
        int q = tid + u * 512;
        float ar = sr[q], ai = si[q], br_ = sr[q + 1024], bi_ = si[q + 1024];
        dr[q] = ar + br_;         di[q] = ai + bi_;
        dr[q + 1024] = ar - br_;  di[q + 1024] = ai - bi_;
    }
    __syncthreads();
}

__global__ __launch_bounds__(512) void hilbert_kernel() {
    __shared__ __align__(16) float Ar[TT], Ai[TT], Br[TT], Bi[TT];
    __shared__ float twr[512], twi[512];
    __shared__ int hist[NBINS];
    int tid = threadIdx.x;
    int rowf = blockIdx.x;
    int rs = rowf / NF, f = rowf % NF;

    {   // twiddles exp(-i*2*pi*k/2048), k<512 (w2,w3 derived by cmul)
        float ang = -2.f * PI_F * (float)tid / 2048.f;
        twr[tid] = cosf(ang); twi[tid] = sinf(ang);
    }
    if (tid < NBINS) hist[tid] = 0;
    const float* src = &g_filt[rowf * TT];
    for (int j = tid; j < TT; j += 512) { Ar[j] = src[j]; Ai[j] = 0.f; }
    __syncthreads();

    fft2048_fwd(Ar, Ai, Br, Bi, twr, twi, tid);

    // spectrum * h (analytic), then conjugate to realize inverse via forward FFT
    for (int k = tid; k < TT; k += 512) {
        float fac = (k == 0 || k == 1024) ? 1.f : (k < 1024 ? 2.f : 0.f);
        Ar[k] =  Ar[k] * fac;
        Ai[k] = -Ai[k] * fac;
    }
    __syncthreads();

    fft2048_fwd(Ar, Ai, Br, Bi, twr, twi, tid);
    // analytic = conj(result) / 2048  (re in Ar, im = -Ai)

    const float scale = 1.f / 2048.f;
    if (f < 10) {
        int prow = rs * 10 + f;
        const float B_OVER_2PI = (float)NBINS / (2.f * PI_F);
        for (int j = tid; j < TT; j += 512) {
            float re = Ar[j];
            float im = -Ai[j];
            float ph = atan2f(im, re);
            int bin = (int)floorf((ph + PI_F) * B_OVER_2PI);
            bin = bin < 0 ? 0 : (bin > NBINS - 1 ? NBINS - 1 : bin);
            g_bin[prow * TT + j] = (unsigned char)bin;
            atomicAdd(&hist[bin], 1);
        }
        __syncthreads();
        if (tid < NBINS) g_cnt[prow * NBINS + tid] = hist[tid];
    } else {
        int arow = rs * 10 + (f - 10);
        for (int j = tid; j < TT; j += 512) {
            float re = Ar[j] * scale, im = Ai[j] * scale;
            g_amp[arow * TT + j] = sqrtf(re * re + im * im);
        }
    }
}

// -------------------- 4) modulation index (predicated reg histograms) ----------
// Reference reshapes (B*C*S, 10, T) -> (B, C, 10, S, T): within (b,c) the flat
// index m = p'*4 + s' maps to underlying (s = m/10, band = m%10). Replicated here.
__global__ __launch_bounds__(256) void mi_kernel(float* __restrict__ out) {
    int a_ = blockIdx.x, p_ = blockIdx.y, z = blockIdx.z;
    int bc = z >> 2, sp = z & 3;
    int mp = p_ * 4 + sp;
    int ma = a_ * 4 + sp;
    int prow = (bc * 4 + mp / 10) * 10 + (mp % 10);
    int arow = (bc * 4 + ma / 10) * 10 + (ma % 10);
    const unsigned char* bp = &g_bin[prow * TT];
    const float* ap = &g_amp[arow * TT];
    int tid = threadIdx.x;

    float acc[NBINS];
#pragma unroll
    for (int b = 0; b < NBINS; b++) acc[b] = 0.f;
#pragma unroll
    for (int i = 0; i < 8; i++) {
        int t = tid + 256 * i;
        int bin = bp[t];
        float av = ap[t];
#pragma unroll
        for (int b = 0; b < NBINS; b++) acc[b] += (bin == b) ? av : 0.f;
    }
#pragma unroll
    for (int b = 0; b < NBINS; b++)
#pragma unroll
        for (int off = 16; off > 0; off >>= 1)
            acc[b] += __shfl_down_sync(0xffffffffu, acc[b], off);

    __shared__ float wred[8][NBINS];
    int wid = tid >> 5, lane = tid & 31;
    if (lane == 0) {
#pragma unroll
        for (int b = 0; b < NBINS; b++) wred[wid][b] = acc[b];
    }
    __syncthreads();

    if (tid == 0) {
        float mean[NBINS];
        float ssum = 0.f;
#pragma unroll
        for (int b = 0; b < NBINS; b++) {
            float v = 0.f;
#pragma unroll
            for (int w = 0; w < 8; w++) v += wred[w][b];
            float c = (float)g_cnt[prow * NBINS + b];
            float m = v / fmaxf(c, 1.f);
            mean[b] = m; ssum += m;
        }
        ssum = fmaxf(ssum, 1e-12f);
        float ent = 0.f;
#pragma unroll
        for (int b = 0; b < NBINS; b++) {
            float pb = mean[b] / ssum;
            ent += pb * logf(fmaxf(pb, 1e-12f));
        }
        const float LOGN = logf((float)NBINS);
        float mi = (LOGN + ent) / LOGN;
        atomicAdd(&out[(bc * 10 + p_) * 10 + a_], 0.25f * mi);
    }
}

// -------------------- launch --------------------
extern "C" void kernel_launch(void* const* d_in, const int* in_sizes, int n_in,
                              void* d_out, int out_size) {
    const float* x = (const float*)d_in[0];
    const float* K = (const float*)d_in[1];
    if (n_in >= 2 && in_sizes[0] == NF * LK) {   // robust to metadata order
        const float* t = x; x = K; K = t;
    }
    pad_kernel<<<NROWS, 256>>>(x);
    conv_kernel<<<dim3(NF, NROWS), 256>>>(K);
    hilbert_kernel<<<NROWS * NF, 512>>>();
    cudaMemsetAsync(d_out, 0, (size_t)out_size * sizeof(float));
    mi_kernel<<<dim3(10, 10, 128), 256>>>((float*)d_out);
}

// round 6
// speedup vs baseline: 1.1224x; 1.1224x over previous
#include <cuda_runtime.h>
#include <math.h>

#define TT 2048
#define NROWS 128
#define NF 20
#define LK 769
#define PADL 384
#define SIGP_LEN 2816   /* TT + 2*384 */
#define NBINS 18
#define PI_F 3.14159265358979f

// -------------------- scratch (no allocs allowed) --------------------
__device__ float g_sigp[NROWS * SIGP_LEN];            // 1.44 MB
__device__ float g_filt[NROWS * NF * TT];             // 21 MB
__device__ unsigned char g_bin[NROWS * 10 * TT];      // 2.6 MB
__device__ float g_amp[NROWS * 10 * TT];              // 10.5 MB
__device__ int   g_cnt[NROWS * 10 * NBINS];
__device__ float g_twr[512], g_twi[512];

// -------------------- 0) twiddle precompute --------------------
__global__ void tw_kernel() {
    int t = threadIdx.x;
    float ang = -2.f * PI_F * (float)t / 2048.f;
    g_twr[t] = cosf(ang);
    g_twi[t] = sinf(ang);
}

// -------------------- 1) reflect pad (effective pad 384/side) --------------------
__global__ void pad_kernel(const float* __restrict__ x) {
    int row = blockIdx.x;
    const float* xr = x + row * TT;
    float* o = g_sigp + row * SIGP_LEN;
    for (int j = threadIdx.x; j < SIGP_LEN; j += blockDim.x) {
        int i = j - PADL;
        int src = (i < 0) ? -i : ((i >= TT) ? (2 * TT - 2 - i) : i);
        o[j] = xr[src];
    }
}

// -------------------- 2) FIR conv, nonzero-trimmed, sliding register window ----
__global__ __launch_bounds__(256) void conv_kernel(const float* __restrict__ Kf) {
    __shared__ __align__(16) float ssig[2832];
    __shared__ __align__(16) float sk[784];
    __shared__ int s_lo, s_hi;
    int f = blockIdx.x, row = blockIdx.y;
    int tid = threadIdx.x;

    for (int j = tid; j < 2832; j += 256)
        ssig[j] = (j < SIGP_LEN) ? g_sigp[row * SIGP_LEN + j] : 0.f;
    for (int j = tid; j < 784; j += 256)
        sk[j] = (j < LK) ? Kf[f * LK + j] : 0.f;
    if (tid == 0) { s_lo = LK; s_hi = 0; }
    __syncthreads();

    int llo = LK, lhi = 0;
    for (int j = tid; j < LK; j += 256)
        if (sk[j] != 0.f) { if (j < llo) llo = j; if (j > lhi) lhi = j; }
    atomicMin(&s_lo, llo);
    atomicMax(&s_hi, lhi);
    __syncthreads();

    int l0 = s_lo & ~7;
    int l1 = (s_hi + 8) & ~7;     // exclusive, covers hi; zero taps are free

    int t0 = tid * 8;             // 8 consecutive outputs per thread
    float acc[8];
#pragma unroll
    for (int r = 0; r < 8; r++) acc[r] = 0.f;

    float s[16];
    {
        float4 v0 = *(const float4*)&ssig[t0 + l0];
        float4 v1 = *(const float4*)&ssig[t0 + l0 + 4];
        s[0]=v0.x; s[1]=v0.y; s[2]=v0.z; s[3]=v0.w;
        s[4]=v1.x; s[5]=v1.y; s[6]=v1.z; s[7]=v1.w;
    }
    for (int l = l0; l < l1; l += 8) {
        float4 v2 = *(const float4*)&ssig[t0 + l + 8];
        float4 v3 = *(const float4*)&ssig[t0 + l + 12];
        s[8]=v2.x;  s[9]=v2.y;  s[10]=v2.z; s[11]=v2.w;
        s[12]=v3.x; s[13]=v3.y; s[14]=v3.z; s[15]=v3.w;
#pragma unroll
        for (int j = 0; j < 8; j++) {
            float kv = sk[l + j];
#pragma unroll
            for (int r = 0; r < 8; r++) acc[r] = fmaf(s[j + r], kv, acc[r]);
        }
#pragma unroll
        for (int i = 0; i < 8; i++) s[i] = s[i + 8];
    }
    float* o = &g_filt[(row * NF + f) * TT + t0];
    *(float4*)&o[0] = make_float4(acc[0], acc[1], acc[2], acc[3]);
    *(float4*)&o[4] = make_float4(acc[4], acc[5], acc[6], acc[7]);
}

// -------------------- 3) 2048-pt radix-4 Stockham FFT + Hilbert ----------------
__device__ __forceinline__ void fft2048_fwd(
    float* Ar, float* Ai, float* Br, float* Bi,
    const float* __restrict__ twr, const float* __restrict__ twi, int tid)
{
    float *sr = Ar, *si = Ai, *dr = Br, *di = Bi;
    int s = 1;
#pragma unroll
    for (int st = 0; st < 5; st++) {
        int b = tid;
        int k1 = b & ~(s - 1);          // p*s < 512
        int bb = b + 3 * k1;            // dst base
        float w1r = twr[k1], w1i = twi[k1];
        float w2r = w1r * w1r - w1i * w1i, w2i = 2.f * w1r * w1i;
        float w3r = w2r * w1r - w2i * w1i, w3i = w2r * w1i + w2i * w1r;

        float ar = sr[b],        ai = si[b];
        float br_ = sr[b + 512], bi_ = si[b + 512];
        float cr = sr[b + 1024], ci = si[b + 1024];
        float er = sr[b + 1536], ei = si[b + 1536];

        float apc_r = ar + cr,  apc_i = ai + ci;
        float amc_r = ar - cr,  amc_i = ai - ci;
        float bpd_r = br_ + er, bpd_i = bi_ + ei;
        float bmd_r = br_ - er, bmd_i = bi_ - ei;

        dr[bb] = apc_r + bpd_r;  di[bb] = apc_i + bpd_i;
        float y1r = amc_r + bmd_i, y1i = amc_i - bmd_r;           // amc - i*bmd
        dr[bb + s]     = y1r * w1r - y1i * w1i;  di[bb + s]     = y1r * w1i + y1i * w1r;
        float y2r = apc_r - bpd_r, y2i = apc_i - bpd_i;
        dr[bb + 2 * s] = y2r * w2r - y2i * w2i;  di[bb + 2 * s] = y2r * w2i + y2i * w2r;
        float y3r = amc_r - bmd_i, y3i = amc_i + bmd_r;           // amc + i*bmd
        dr[bb + 3 * s] = y3r * w3r - y3i * w3i;  di[bb + 3 * s] = y3r * w3i + y3i * w3r;
        __syncthreads();
        float* t;
        t = sr; sr = dr; dr = t;
        t = si; si = di; di = t;
        s <<= 2;
    }
    // radix-2 final stage (twiddle = 1); reads sr(=B), writes dr(=A)
#pragma unroll
    for (int u = 0; u < 2; u++) {
        int q = tid + u * 512;
        float ar = sr[q], ai = si[q], br_ = sr[q + 1024], bi_ = si[q + 1024];
        dr[q] = ar + br_;         di[q] = ai + bi_;
        dr[q + 1024] = ar - br_;  di[q + 1024] = ai - bi_;
    }
    __syncthreads();
}

__global__ __launch_bounds__(512) void hilbert_kernel() {
    __shared__ __align__(16) float Ar[TT], Ai[TT], Br[TT], Bi[TT];
    __shared__ float twr[512], twi[512];
    __shared__ int hist[NBINS];
    int tid = threadIdx.x;
    int rowf = blockIdx.x;
    int rs = rowf / NF, f = rowf % NF;

    twr[tid] = g_twr[tid];
    twi[tid] = g_twi[tid];
    if (tid < NBINS) hist[tid] = 0;
    const float* src = &g_filt[rowf * TT];
    for (int j = tid; j < TT; j += 512) { Ar[j] = src[j]; Ai[j] = 0.f; }
    __syncthreads();

    fft2048_fwd(Ar, Ai, Br, Bi, twr, twi, tid);

    // spectrum * h (analytic), then conjugate to realize inverse via forward FFT
    for (int k = tid; k < TT; k += 512) {
        float fac = (k == 0 || k == 1024) ? 1.f : (k < 1024 ? 2.f : 0.f);
        Ar[k] =  Ar[k] * fac;
        Ai[k] = -Ai[k] * fac;
    }
    __syncthreads();

    fft2048_fwd(Ar, Ai, Br, Bi, twr, twi, tid);
    // analytic = conj(result) / 2048  (re in Ar, im = -Ai)

    const float scale = 1.f / 2048.f;
    if (f < 10) {
        int prow = rs * 10 + f;
        const float B_OVER_2PI = (float)NBINS / (2.f * PI_F);
        for (int j = tid; j < TT; j += 512) {
            float re = Ar[j];
            float im = -Ai[j];
            float ph = atan2f(im, re);
            int bin = (int)floorf((ph + PI_F) * B_OVER_2PI);
            bin = bin < 0 ? 0 : (bin > NBINS - 1 ? NBINS - 1 : bin);
            g_bin[prow * TT + j] = (unsigned char)bin;
            atomicAdd(&hist[bin], 1);
        }
        __syncthreads();
        if (tid < NBINS) g_cnt[prow * NBINS + tid] = hist[tid];
    } else {
        int arow = rs * 10 + (f - 10);
        for (int j = tid; j < TT; j += 512) {
            float re = Ar[j] * scale, im = Ai[j] * scale;
            g_amp[arow * TT + j] = sqrtf(re * re + im * im);
        }
    }
}

// -------------------- 4) modulation index v2 ----------------------------------
// Block = (ag, p_, z): one pha row, 5 amp rows. Shared per-thread-slice
// accumulators red[(a*18+bin)*128 + tid]: bank index = tid for every (a,bin)
// -> conflict-free. One bin decode amortized over 5 amp bands; flat tree reduce.
__global__ __launch_bounds__(128) void mi_kernel(float* __restrict__ out) {
    __shared__ float red[90 * 128];   // 46080 B
    int tid = threadIdx.x;
    int ag = blockIdx.x, p_ = blockIdx.y, z = blockIdx.z;
    int bc = z >> 2, sp = z & 3;
    int mp = p_ * 4 + sp;
    int prow = (bc * 4 + mp / 10) * 10 + (mp % 10);
    const unsigned char* bp = g_bin + prow * TT;

    const float* ap[5];
#pragma unroll
    for (int ai = 0; ai < 5; ai++) {
        int ma = (ag * 5 + ai) * 4 + sp;
        int arow = (bc * 4 + ma / 10) * 10 + (ma % 10);
        ap[ai] = g_amp + arow * TT;
    }

#pragma unroll
    for (int j = 0; j < 90; j++) red[j * 128 + tid] = 0.f;
    __syncthreads();

    int t0 = tid * 16;  // 16 contiguous samples per thread
#pragma unroll
    for (int c = 0; c < 4; c++) {
        uchar4 b4 = *(const uchar4*)(bp + t0 + c * 4);
        int i0 = (int)b4.x * 128 + tid;
        int i1 = (int)b4.y * 128 + tid;
        int i2 = (int)b4.z * 128 + tid;
        int i3 = (int)b4.w * 128 + tid;
#pragma unroll
        for (int ai = 0; ai < 5; ai++) {
            float4 v = *(const float4*)(ap[ai] + t0 + c * 4);
            int base = ai * (18 * 128);
            red[base + i0] += v.x;
            red[base + i1] += v.y;
            red[base + i2] += v.z;
            red[base + i3] += v.w;
        }
    }
    __syncthreads();

    // flat tree reduction over the 128-lane dimension for all 90 (a,bin) slots
#pragma unroll
    for (int sh = 6; sh >= 0; sh--) {
        int s = 1 << sh;
        for (int k = tid; k < 90 * s; k += 128) {
            int j = k >> sh;
            int t = k & (s - 1);
            red[j * 128 + t] += red[j * 128 + t + s];
        }
        __syncthreads();
    }

    if (tid < 5) {
        int a = tid;
        float mean[NBINS];
        float ssum = 0.f;
#pragma unroll
        for (int b = 0; b < NBINS; b++) {
            float v = red[(a * 18 + b) * 128];
            float c = (float)g_cnt[prow * NBINS + b];
            float m = v / fmaxf(c, 1.f);
            mean[b] = m; ssum += m;
        }
        ssum = fmaxf(ssum, 1e-12f);
        float ent = 0.f;
#pragma unroll
        for (int b = 0; b < NBINS; b++) {
            float pb = mean[b] / ssum;
            ent += pb * logf(fmaxf(pb, 1e-12f));
        }
        const float LOGN = logf((float)NBINS);
        float mi = (LOGN + ent) / LOGN;
        int a_ = ag * 5 + a;
        atomicAdd(&out[(bc * 10 + p_) * 10 + a_], 0.25f * mi);
    }
}

// -------------------- launch --------------------
extern "C" void kernel_launch(void* const* d_in, const int* in_sizes, int n_in,
                              void* d_out, int out_size) {
    const float* x = (const float*)d_in[0];
    const float* K = (const float*)d_in[1];
    if (n_in >= 2 && in_sizes[0] == NF * LK) {   // robust to metadata order
        const float* t = x; x = K; K = t;
    }
    tw_kernel<<<1, 512>>>();
    pad_kernel<<<NROWS, 256>>>(x);
    conv_kernel<<<dim3(NF, NROWS), 256>>>(K);
    hilbert_kernel<<<NROWS * NF, 512>>>();
    cudaMemsetAsync(d_out, 0, (size_t)out_size * sizeof(float));
    mi_kernel<<<dim3(2, 10, 128), 128>>>((float*)d_out);
}

// round 7
// speedup vs baseline: 1.1464x; 1.0213x over previous
#include <cuda_runtime.h>
#include <math.h>

#define TT 2048
#define NROWS 128
#define NF 20
#define LK 769
#define PADL 384
#define SIGP_LEN 2816   /* TT + 2*384 */
#define NBINS 18
#define PI_F 3.14159265358979f

// -------------------- scratch (no allocs allowed) --------------------
__device__ float g_sigp[NROWS * SIGP_LEN];            // 1.44 MB
__device__ float g_filt[NROWS * NF * TT];             // 21 MB
__device__ unsigned char g_bin[NROWS * 10 * TT];      // 2.6 MB
__device__ float g_amp[NROWS * 10 * TT];              // 10.5 MB
__device__ int   g_cnt[NROWS * 10 * NBINS];
__device__ float g_twr[512], g_twi[512];

// -------------------- 0) twiddle precompute --------------------
__global__ void tw_kernel() {
    int t = threadIdx.x;
    float ang = -2.f * PI_F * (float)t / 2048.f;
    g_twr[t] = cosf(ang);
    g_twi[t] = sinf(ang);
}

// -------------------- 1) reflect pad (effective pad 384/side) --------------------
__global__ void pad_kernel(const float* __restrict__ x) {
    int row = blockIdx.x;
    const float* xr = x + row * TT;
    float* o = g_sigp + row * SIGP_LEN;
    for (int j = threadIdx.x; j < SIGP_LEN; j += blockDim.x) {
        int i = j - PADL;
        int src = (i < 0) ? -i : ((i >= TT) ? (2 * TT - 2 - i) : i);
        o[j] = xr[src];
    }
}

// -------------------- 2) FIR conv, nonzero-trimmed, sliding register window ----
__global__ __launch_bounds__(256) void conv_kernel(const float* __restrict__ Kf) {
    __shared__ __align__(16) float ssig[2832];
    __shared__ __align__(16) float sk[784];
    __shared__ int s_lo, s_hi;
    int f = blockIdx.x, row = blockIdx.y;
    int tid = threadIdx.x;

    for (int j = tid; j < 2832; j += 256)
        ssig[j] = (j < SIGP_LEN) ? g_sigp[row * SIGP_LEN + j] : 0.f;
    for (int j = tid; j < 784; j += 256)
        sk[j] = (j < LK) ? Kf[f * LK + j] : 0.f;
    if (tid == 0) { s_lo = LK; s_hi = 0; }
    __syncthreads();

    int llo = LK, lhi = 0;
    for (int j = tid; j < LK; j += 256)
        if (sk[j] != 0.f) { if (j < llo) llo = j; if (j > lhi) lhi = j; }
    atomicMin(&s_lo, llo);
    atomicMax(&s_hi, lhi);
    __syncthreads();

    int l0 = s_lo & ~7;
    int l1 = (s_hi + 8) & ~7;     // exclusive, covers hi; zero taps are free

    int t0 = tid * 8;             // 8 consecutive outputs per thread
    float acc[8];
#pragma unroll
    for (int r = 0; r < 8; r++) acc[r] = 0.f;

    float s[16];
    {
        float4 v0 = *(const float4*)&ssig[t0 + l0];
        float4 v1 = *(const float4*)&ssig[t0 + l0 + 4];
        s[0]=v0.x; s[1]=v0.y; s[2]=v0.z; s[3]=v0.w;
        s[4]=v1.x; s[5]=v1.y; s[6]=v1.z; s[7]=v1.w;
    }
    for (int l = l0; l < l1; l += 8) {
        float4 v2 = *(const float4*)&ssig[t0 + l + 8];
        float4 v3 = *(const float4*)&ssig[t0 + l + 12];
        s[8]=v2.x;  s[9]=v2.y;  s[10]=v2.z; s[11]=v2.w;
        s[12]=v3.x; s[13]=v3.y; s[14]=v3.z; s[15]=v3.w;
#pragma unroll
        for (int j = 0; j < 8; j++) {
            float kv = sk[l + j];
#pragma unroll
            for (int r = 0; r < 8; r++) acc[r] = fmaf(s[j + r], kv, acc[r]);
        }
#pragma unroll
        for (int i = 0; i < 8; i++) s[i] = s[i + 8];
    }
    float* o = &g_filt[(row * NF + f) * TT + t0];
    *(float4*)&o[0] = make_float4(acc[0], acc[1], acc[2], acc[3]);
    *(float4*)&o[4] = make_float4(acc[4], acc[5], acc[6], acc[7]);
}

// -------------------- 3) 2048-pt radix-8 Stockham FFT (in-place, padded) -------
// IDX pad: i + (i>>3). Bank check: s=1 writes -> banks (9t+j)%32 (9 coprime 32,
// distinct); s=8 writes -> (8q+r+9j)%32 (8q+r spans 0..31, distinct); s=64 and
// final r4 warp-consecutive. Two syncs per stage (read-all / write-all).
#define IDX(i) ((i) + ((i) >> 3))

__device__ __forceinline__ void fft2048_r8(
    float* Sr, float* Si,
    const float* __restrict__ twr, const float* __restrict__ twi, int tid)
{
    const float C = 0.70710678118654752f;
    int s = 1;
#pragma unroll
    for (int st = 0; st < 3; st++) {
        int b = tid;
        int k1 = b & ~(s - 1);
        int d  = b & (s - 1);
        int base = 8 * k1 + d;

        float xr[8], xi[8];
#pragma unroll
        for (int m = 0; m < 8; m++) {
            xr[m] = Sr[IDX(b + m * 256)];
            xi[m] = Si[IDX(b + m * 256)];
        }
        __syncthreads();

        float a0r=xr[0]+xr[4], a0i=xi[0]+xi[4];
        float a1r=xr[0]-xr[4], a1i=xi[0]-xi[4];
        float a2r=xr[2]+xr[6], a2i=xi[2]+xi[6];
        float a3r=xr[2]-xr[6], a3i=xi[2]-xi[6];
        float a4r=xr[1]+xr[5], a4i=xi[1]+xi[5];
        float a5r=xr[1]-xr[5], a5i=xi[1]-xi[5];
        float a6r=xr[3]+xr[7], a6i=xi[3]+xi[7];
        float a7r=xr[3]-xr[7], a7i=xi[3]-xi[7];
        float t3r =  a3i, t3i = -a3r;          // -i * a3
        float t7r =  a7i, t7i = -a7r;          // -i * a7
        float b0r=a0r+a2r, b0i=a0i+a2i;
        float b1r=a0r-a2r, b1i=a0i-a2i;
        float b2r=a1r+t3r, b2i=a1i+t3i;
        float b3r=a1r-t3r, b3i=a1i-t3i;
        float b4r=a4r+a6r, b4i=a4i+a6i;
        float b5r=a4r-a6r, b5i=a4i-a6i;
        float b6r=a5r+t7r, b6i=a5i+t7i;
        float b7r=a5r-t7r, b7i=a5i-t7i;
        float o1r =  C*(b6r + b6i), o1i =  C*(b6i - b6r);   // w8^1 * b6
        float o3r =  C*(b7i - b7r), o3i = -C*(b7r + b7i);   // w8^3 * b7

        float yr[8], yi[8];
        yr[0]=b0r+b4r; yi[0]=b0i+b4i;
        yr[4]=b0r-b4r; yi[4]=b0i-b4i;
        yr[1]=b2r+o1r; yi[1]=b2i+o1i;
        yr[5]=b2r-o1r; yi[5]=b2i-o1i;
        yr[2]=b1r+b5i; yi[2]=b1i-b5r;          // + (-i)*b5
        yr[6]=b1r-b5i; yi[6]=b1i+b5r;
        yr[3]=b3r+o3r; yi[3]=b3i+o3i;
        yr[7]=b3r-o3r; yi[7]=b3i-o3i;

        float w1r = twr[k1], w1i = twi[k1];
        float wr = w1r, wi = w1i;
        Sr[IDX(base)] = yr[0]; Si[IDX(base)] = yi[0];
#pragma unroll
        for (int j = 1; j < 8; j++) {
            float vr = yr[j]*wr - yi[j]*wi;
            float vi = yr[j]*wi + yi[j]*wr;
            Sr[IDX(base + j*s)] = vr; Si[IDX(base + j*s)] = vi;
            float nr = wr*w1r - wi*w1i;
            wi = wr*w1i + wi*w1r; wr = nr;
        }
        __syncthreads();
        s <<= 3;
    }
    // final radix-4 stage, s=512, k1=0 -> unit twiddles; 2 butterflies/thread
    float rr[2][4], ri[2][4];
#pragma unroll
    for (int u = 0; u < 2; u++) {
        int b = tid + u * 256;
#pragma unroll
        for (int m = 0; m < 4; m++) {
            rr[u][m] = Sr[IDX(b + m * 512)];
            ri[u][m] = Si[IDX(b + m * 512)];
        }
    }
    __syncthreads();
#pragma unroll
    for (int u = 0; u < 2; u++) {
        int b = tid + u * 256;
        float apc_r = rr[u][0]+rr[u][2], apc_i = ri[u][0]+ri[u][2];
        float amc_r = rr[u][0]-rr[u][2], amc_i = ri[u][0]-ri[u][2];
        float bpd_r = rr[u][1]+rr[u][3], bpd_i = ri[u][1]+ri[u][3];
        float bmd_r = rr[u][1]-rr[u][3], bmd_i = ri[u][1]-ri[u][3];
        Sr[IDX(b)]        = apc_r + bpd_r;  Si[IDX(b)]        = apc_i + bpd_i;
        Sr[IDX(b +  512)] = amc_r + bmd_i;  Si[IDX(b +  512)] = amc_i - bmd_r;
        Sr[IDX(b + 1024)] = apc_r - bpd_r;  Si[IDX(b + 1024)] = apc_i - bpd_i;
        Sr[IDX(b + 1536)] = amc_r - bmd_i;  Si[IDX(b + 1536)] = amc_i + bmd_r;
    }
    __syncthreads();
}

__global__ __launch_bounds__(256) void hilbert_kernel() {
    __shared__ __align__(16) float Sr[2304], Si[2304];
    __shared__ float twr[256], twi[256];
    __shared__ int hist[NBINS];
    int tid = threadIdx.x;
    int rowf = blockIdx.x;
    int rs = rowf / NF, f = rowf % NF;

    twr[tid] = g_twr[tid];
    twi[tid] = g_twi[tid];
    if (tid < NBINS) hist[tid] = 0;
    const float* src = &g_filt[rowf * TT];
    for (int j = tid; j < TT; j += 256) { Sr[IDX(j)] = src[j]; Si[IDX(j)] = 0.f; }
    __syncthreads();

    fft2048_r8(Sr, Si, twr, twi, tid);

    // spectrum * h (analytic), then conjugate to realize inverse via forward FFT
    for (int k = tid; k < TT; k += 256) {
        float fac = (k == 0 || k == 1024) ? 1.f : (k < 1024 ? 2.f : 0.f);
        int p = IDX(k);
        Sr[p] =  Sr[p] * fac;
        Si[p] = -Si[p] * fac;
    }
    __syncthreads();

    fft2048_r8(Sr, Si, twr, twi, tid);
    // analytic = conj(result) / 2048  (re in Sr, im = -Si)

    const float scale = 1.f / 2048.f;
    if (f < 10) {
        int prow = rs * 10 + f;
        const float B_OVER_2PI = (float)NBINS / (2.f * PI_F);
        for (int j = tid; j < TT; j += 256) {
            float re =  Sr[IDX(j)];
            float im = -Si[IDX(j)];
            float ph = atan2f(im, re);
            int bin = (int)floorf((ph + PI_F) * B_OVER_2PI);
            bin = bin < 0 ? 0 : (bin > NBINS - 1 ? NBINS - 1 : bin);
            g_bin[prow * TT + j] = (unsigned char)bin;
            atomicAdd(&hist[bin], 1);
        }
        __syncthreads();
        if (tid < NBINS) g_cnt[prow * NBINS + tid] = hist[tid];
    } else {
        int arow = rs * 10 + (f - 10);
        for (int j = tid; j < TT; j += 256) {
            float re = Sr[IDX(j)] * scale, im = Si[IDX(j)] * scale;
            g_amp[arow * TT + j] = sqrtf(re * re + im * im);
        }
    }
}

// -------------------- 4) modulation index v2 ----------------------------------
__global__ __launch_bounds__(128) void mi_kernel(float* __restrict__ out) {
    __shared__ float red[90 * 128];   // 46080 B
    int tid = threadIdx.x;
    int ag = blockIdx.x, p_ = blockIdx.y, z = blockIdx.z;
    int bc = z >> 2, sp = z & 3;
    int mp = p_ * 4 + sp;
    int prow = (bc * 4 + mp / 10) * 10 + (mp % 10);
    const unsigned char* bp = g_bin + prow * TT;

    const float* ap[5];
#pragma unroll
    for (int ai = 0; ai < 5; ai++) {
        int ma = (ag * 5 + ai) * 4 + sp;
        int arow = (bc * 4 + ma / 10) * 10 + (ma % 10);
        ap[ai] = g_amp + arow * TT;
    }

#pragma unroll
    for (int j = 0; j < 90; j++) red[j * 128 + tid] = 0.f;
    __syncthreads();

    int t0 = tid * 16;  // 16 contiguous samples per thread
#pragma unroll
    for (int c = 0; c < 4; c++) {
        uchar4 b4 = *(const uchar4*)(bp + t0 + c * 4);
        int i0 = (int)b4.x * 128 + tid;
        int i1 = (int)b4.y * 128 + tid;
        int i2 = (int)b4.z * 128 + tid;
        int i3 = (int)b4.w * 128 + tid;
#pragma unroll
        for (int ai = 0; ai < 5; ai++) {
            float4 v = *(const float4*)(ap[ai] + t0 + c * 4);
            int base = ai * (18 * 128);
            red[base + i0] += v.x;
            red[base + i1] += v.y;
            red[base + i2] += v.z;
            red[base + i3] += v.w;
        }
    }
    __syncthreads();

#pragma unroll
    for (int sh = 6; sh >= 0; sh--) {
        int s = 1 << sh;
        for (int k = tid; k < 90 * s; k += 128) {
            int j = k >> sh;
            int t = k & (s - 1);
            red[j * 128 + t] += red[j * 128 + t + s];
        }
        __syncthreads();
    }

    if (tid < 5) {
        int a = tid;
        float mean[NBINS];
        float ssum = 0.f;
#pragma unroll
        for (int b = 0; b < NBINS; b++) {
            float v = red[(a * 18 + b) * 128];
            float c = (float)g_cnt[prow * NBINS + b];
            float m = v / fmaxf(c, 1.f);
            mean[b] = m; ssum += m;
        }
        ssum = fmaxf(ssum, 1e-12f);
        float ent = 0.f;
#pragma unroll
        for (int b = 0; b < NBINS; b++) {
            float pb = mean[b] / ssum;
            ent += pb * logf(fmaxf(pb, 1e-12f));
        }
        const float LOGN = logf((float)NBINS);
        float mi = (LOGN + ent) / LOGN;
        int a_ = ag * 5 + a;
        atomicAdd(&out[(bc * 10 + p_) * 10 + a_], 0.25f * mi);
    }
}

// -------------------- launch --------------------
extern "C" void kernel_launch(void* const* d_in, const int* in_sizes, int n_in,
                              void* d_out, int out_size) {
    const float* x = (const float*)d_in[0];
    const float* K = (const float*)d_in[1];
    if (n_in >= 2 && in_sizes[0] == NF * LK) {   // robust to metadata order
        const float* t = x; x = K; K = t;
    }
    tw_kernel<<<1, 512>>>();
    pad_kernel<<<NROWS, 256>>>(x);
    conv_kernel<<<dim3(NF, NROWS), 256>>>(K);
    hilbert_kernel<<<NROWS * NF, 256>>>();
    cudaMemsetAsync(d_out, 0, (size_t)out_size * sizeof(float));
    mi_kernel<<<dim3(2, 10, 128), 128>>>((float*)d_out);
}

// round 8
// speedup vs baseline: 1.2698x; 1.1077x over previous
#include <cuda_runtime.h>
#include <math.h>

#define TT 2048
#define NROWS 128
#define NF 20
#define LK 769
#define PADL 384
#define SIGP_LEN 2816   /* TT + 2*384 */
#define NBINS 18
#define PI_F 3.14159265358979f

// -------------------- scratch (no allocs allowed) --------------------
__device__ float g_sigp[NROWS * SIGP_LEN];            // 1.44 MB
__device__ float g_filt[NROWS * NF * TT];             // 21 MB
__device__ unsigned char g_bin[NROWS * 10 * TT];      // 2.6 MB
__device__ float g_amp[NROWS * 10 * TT];              // 10.5 MB
__device__ int   g_cnt[NROWS * 10 * NBINS];
__device__ float g_twr[512], g_twi[512];

// -------------------- 0) twiddle precompute --------------------
__global__ void tw_kernel() {
    int t = threadIdx.x;
    float ang = -2.f * PI_F * (float)t / 2048.f;
    g_twr[t] = cosf(ang);
    g_twi[t] = sinf(ang);
}

// -------------------- 1) reflect pad (effective pad 384/side) --------------------
__global__ void pad_kernel(const float* __restrict__ x) {
    int row = blockIdx.x;
    const float* xr = x + row * TT;
    float* o = g_sigp + row * SIGP_LEN;
    for (int j = threadIdx.x; j < SIGP_LEN; j += blockDim.x) {
        int i = j - PADL;
        int src = (i < 0) ? -i : ((i >= TT) ? (2 * TT - 2 - i) : i);
        o[j] = xr[src];
    }
}

// -------------------- 2) FIR conv, nonzero-trimmed, sliding register window ----
__global__ __launch_bounds__(256) void conv_kernel(const float* __restrict__ Kf) {
    __shared__ __align__(16) float ssig[2832];
    __shared__ __align__(16) float sk[784];
    __shared__ int s_lo, s_hi;
    int f = blockIdx.x, row = blockIdx.y;
    int tid = threadIdx.x;

    for (int j = tid; j < 2832; j += 256)
        ssig[j] = (j < SIGP_LEN) ? g_sigp[row * SIGP_LEN + j] : 0.f;
    for (int j = tid; j < 784; j += 256)
        sk[j] = (j < LK) ? Kf[f * LK + j] : 0.f;
    if (tid == 0) { s_lo = LK; s_hi = 0; }
    __syncthreads();

    int llo = LK, lhi = 0;
    for (int j = tid; j < LK; j += 256)
        if (sk[j] != 0.f) { if (j < llo) llo = j; if (j > lhi) lhi = j; }
    atomicMin(&s_lo, llo);
    atomicMax(&s_hi, lhi);
    __syncthreads();

    int l0 = s_lo & ~7;
    int l1 = (s_hi + 8) & ~7;     // exclusive, covers hi; zero taps are free

    int t0 = tid * 8;             // 8 consecutive outputs per thread
    float acc[8];
#pragma unroll
    for (int r = 0; r < 8; r++) acc[r] = 0.f;

    float s[16];
    {
        float4 v0 = *(const float4*)&ssig[t0 + l0];
        float4 v1 = *(const float4*)&ssig[t0 + l0 + 4];
        s[0]=v0.x; s[1]=v0.y; s[2]=v0.z; s[3]=v0.w;
        s[4]=v1.x; s[5]=v1.y; s[6]=v1.z; s[7]=v1.w;
    }
    for (int l = l0; l < l1; l += 8) {
        float4 v2 = *(const float4*)&ssig[t0 + l + 8];
        float4 v3 = *(const float4*)&ssig[t0 + l + 12];
        s[8]=v2.x;  s[9]=v2.y;  s[10]=v2.z; s[11]=v2.w;
        s[12]=v3.x; s[13]=v3.y; s[14]=v3.z; s[15]=v3.w;
#pragma unroll
        for (int j = 0; j < 8; j++) {
            float kv = sk[l + j];
#pragma unroll
            for (int r = 0; r < 8; r++) acc[r] = fmaf(s[j + r], kv, acc[r]);
        }
#pragma unroll
        for (int i = 0; i < 8; i++) s[i] = s[i + 8];
    }
    float* o = &g_filt[(row * NF + f) * TT + t0];
    *(float4*)&o[0] = make_float4(acc[0], acc[1], acc[2], acc[3]);
    *(float4*)&o[4] = make_float4(acc[4], acc[5], acc[6], acc[7]);
}

// -------------------- 3) 2048-pt radix-8 Stockham FFT (in-place, padded) -------
#define IDX(i) ((i) + ((i) >> 3))

__device__ __forceinline__ void fft2048_r8(
    float* Sr, float* Si,
    const float* __restrict__ twr, const float* __restrict__ twi, int tid)
{
    const float C = 0.70710678118654752f;
    int s = 1;
#pragma unroll
    for (int st = 0; st < 3; st++) {
        int b = tid;
        int k1 = b & ~(s - 1);
        int d  = b & (s - 1);
        int base = 8 * k1 + d;

        float xr[8], xi[8];
#pragma unroll
        for (int m = 0; m < 8; m++) {
            xr[m] = Sr[IDX(b + m * 256)];
            xi[m] = Si[IDX(b + m * 256)];
        }
        __syncthreads();

        float a0r=xr[0]+xr[4], a0i=xi[0]+xi[4];
        float a1r=xr[0]-xr[4], a1i=xi[0]-xi[4];
        float a2r=xr[2]+xr[6], a2i=xi[2]+xi[6];
        float a3r=xr[2]-xr[6], a3i=xi[2]-xi[6];
        float a4r=xr[1]+xr[5], a4i=xi[1]+xi[5];
        float a5r=xr[1]-xr[5], a5i=xi[1]-xi[5];
        float a6r=xr[3]+xr[7], a6i=xi[3]+xi[7];
        float a7r=xr[3]-xr[7], a7i=xi[3]-xi[7];
        float t3r =  a3i, t3i = -a3r;          // -i * a3
        float t7r =  a7i, t7i = -a7r;          // -i * a7
        float b0r=a0r+a2r, b0i=a0i+a2i;
        float b1r=a0r-a2r, b1i=a0i-a2i;
        float b2r=a1r+t3r, b2i=a1i+t3i;
        float b3r=a1r-t3r, b3i=a1i-t3i;
        float b4r=a4r+a6r, b4i=a4i+a6i;
        float b5r=a4r-a6r, b5i=a4i-a6i;
        float b6r=a5r+t7r, b6i=a5i+t7i;
        float b7r=a5r-t7r, b7i=a5i-t7i;
        float o1r =  C*(b6r + b6i), o1i =  C*(b6i - b6r);   // w8^1 * b6
        float o3r =  C*(b7i - b7r), o3i = -C*(b7r + b7i);   // w8^3 * b7

        float yr[8], yi[8];
        yr[0]=b0r+b4r; yi[0]=b0i+b4i;
        yr[4]=b0r-b4r; yi[4]=b0i-b4i;
        yr[1]=b2r+o1r; yi[1]=b2i+o1i;
        yr[5]=b2r-o1r; yi[5]=b2i-o1i;
        yr[2]=b1r+b5i; yi[2]=b1i-b5r;          // + (-i)*b5
        yr[6]=b1r-b5i; yi[6]=b1i+b5r;
        yr[3]=b3r+o3r; yi[3]=b3i+o3i;
        yr[7]=b3r-o3r; yi[7]=b3i-o3i;

        float w1r = twr[k1], w1i = twi[k1];
        float wr = w1r, wi = w1i;
        Sr[IDX(base)] = yr[0]; Si[IDX(base)] = yi[0];
#pragma unroll
        for (int j = 1; j < 8; j++) {
            float vr = yr[j]*wr - yi[j]*wi;
            float vi = yr[j]*wi + yi[j]*wr;
            Sr[IDX(base + j*s)] = vr; Si[IDX(base + j*s)] = vi;
            float nr = wr*w1r - wi*w1i;
            wi = wr*w1i + wi*w1r; wr = nr;
        }
        __syncthreads();
        s <<= 3;
    }
    // final radix-4 stage, s=512, k1=0 -> unit twiddles; 2 butterflies/thread
    float rr[2][4], ri[2][4];
#pragma unroll
    for (int u = 0; u < 2; u++) {
        int b = tid + u * 256;
#pragma unroll
        for (int m = 0; m < 4; m++) {
            rr[u][m] = Sr[IDX(b + m * 512)];
            ri[u][m] = Si[IDX(b + m * 512)];
        }
    }
    __syncthreads();
#pragma unroll
    for (int u = 0; u < 2; u++) {
        int b = tid + u * 256;
        float apc_r = rr[u][0]+rr[u][2], apc_i = ri[u][0]+ri[u][2];
        float amc_r = rr[u][0]-rr[u][2], amc_i = ri[u][0]-ri[u][2];
        float bpd_r = rr[u][1]+rr[u][3], bpd_i = ri[u][1]+ri[u][3];
        float bmd_r = rr[u][1]-rr[u][3], bmd_i = ri[u][1]-ri[u][3];
        Sr[IDX(b)]        = apc_r + bpd_r;  Si[IDX(b)]        = apc_i + bpd_i;
        Sr[IDX(b +  512)] = amc_r + bmd_i;  Si[IDX(b +  512)] = amc_i - bmd_r;
        Sr[IDX(b + 1024)] = apc_r - bpd_r;  Si[IDX(b + 1024)] = apc_i - bpd_i;
        Sr[IDX(b + 1536)] = amc_r - bmd_i;  Si[IDX(b + 1536)] = amc_i + bmd_r;
    }
    __syncthreads();
}

// Packed dual-signal Hilbert: z = x + i*y, one fwd FFT, multiplier -i*sgn(k),
// one inv FFT (conj-fwd-conj) -> Hx = Re, Hy = Im. Phase/amp use exact x,y.
__global__ __launch_bounds__(256) void hilbert_kernel() {
    __shared__ __align__(16) float Sr[2304], Si[2304];
    __shared__ float twr[256], twi[256];
    __shared__ int hist[NBINS];
    int tid = threadIdx.x;
    int pb = blockIdx.x;            // 0..1279
    int row = pb / 10, fp = pb % 10;

    twr[tid] = g_twr[tid];
    twi[tid] = g_twi[tid];
    if (tid < NBINS) hist[tid] = 0;

    const float* xs = &g_filt[(row * NF + fp) * TT];        // pha-band signal
    const float* ys = &g_filt[(row * NF + fp + 10) * TT];   // amp-band signal
    for (int j = tid; j < TT; j += 256) {
        Sr[IDX(j)] = xs[j];
        Si[IDX(j)] = ys[j];
    }
    __syncthreads();

    fft2048_r8(Sr, Si, twr, twi, tid);

    // W = conj(-i*sgn(k) * Z):  k in 1..1023 -> (Zi, Zr); 1025..2047 -> (-Zi,-Zr);
    // k = 0, 1024 -> 0. Then inverse = conj(fft(W))/N.
    for (int k = tid; k < TT; k += 256) {
        float sg = (k == 0 || k == 1024) ? 0.f : (k < 1024 ? 1.f : -1.f);
        int p = IDX(k);
        float zr = Sr[p], zi = Si[p];
        Sr[p] = sg * zi;
        Si[p] = sg * zr;
    }
    __syncthreads();

    fft2048_r8(Sr, Si, twr, twi, tid);
    // Hx = Sr/N,  Hy = -Si/N

    const float scale = 1.f / 2048.f;
    const float B_OVER_2PI = (float)NBINS / (2.f * PI_F);
    int orow = row * 10 + fp;       // same index for pha and amp outputs
    for (int j = tid; j < TT; j += 256) {
        int p = IDX(j);
        float hx = Sr[p] * scale;
        float hy = -Si[p] * scale;
        // phase band
        float re = xs[j];
        float ph = atan2f(hx, re);
        int bin = (int)floorf((ph + PI_F) * B_OVER_2PI);
        bin = bin < 0 ? 0 : (bin > NBINS - 1 ? NBINS - 1 : bin);
        g_bin[orow * TT + j] = (unsigned char)bin;
        atomicAdd(&hist[bin], 1);
        // amplitude band
        float ay = ys[j];
        g_amp[orow * TT + j] = sqrtf(ay * ay + hy * hy);
    }
    __syncthreads();
    if (tid < NBINS) g_cnt[orow * NBINS + tid] = hist[tid];
}

// -------------------- 4) modulation index v2 ----------------------------------
__global__ __launch_bounds__(128) void mi_kernel(float* __restrict__ out) {
    __shared__ float red[90 * 128];   // 46080 B
    int tid = threadIdx.x;
    int ag = blockIdx.x, p_ = blockIdx.y, z = blockIdx.z;
    int bc = z >> 2, sp = z & 3;
    int mp = p_ * 4 + sp;
    int prow = (bc * 4 + mp / 10) * 10 + (mp % 10);
    const unsigned char* bp = g_bin + prow * TT;

    const float* ap[5];
#pragma unroll
    for (int ai = 0; ai < 5; ai++) {
        int ma = (ag * 5 + ai) * 4 + sp;
        int arow = (bc * 4 + ma / 10) * 10 + (ma % 10);
        ap[ai] = g_amp + arow * TT;
    }

#pragma unroll
    for (int j = 0; j < 90; j++) red[j * 128 + tid] = 0.f;
    __syncthreads();

    int t0 = tid * 16;  // 16 contiguous samples per thread
#pragma unroll
    for (int c = 0; c < 4; c++) {
        uchar4 b4 = *(const uchar4*)(bp + t0 + c * 4);
        int i0 = (int)b4.x * 128 + tid;
        int i1 = (int)b4.y * 128 + tid;
        int i2 = (int)b4.z * 128 + tid;
        int i3 = (int)b4.w * 128 + tid;
#pragma unroll
        for (int ai = 0; ai < 5; ai++) {
            float4 v = *(const float4*)(ap[ai] + t0 + c * 4);
            int base = ai * (18 * 128);
            red[base + i0] += v.x;
            red[base + i1] += v.y;
            red[base + i2] += v.z;
            red[base + i3] += v.w;
        }
    }
    __syncthreads();

#pragma unroll
    for (int sh = 6; sh >= 0; sh--) {
        int s = 1 << sh;
        for (int k = tid; k < 90 * s; k += 128) {
            int j = k >> sh;
            int t = k & (s - 1);
            red[j * 128 + t] += red[j * 128 + t + s];
        }
        __syncthreads();
    }

    if (tid < 5) {
        int a = tid;
        float mean[NBINS];
        float ssum = 0.f;
#pragma unroll
        for (int b = 0; b < NBINS; b++) {
            float v = red[(a * 18 + b) * 128];
            float c = (float)g_cnt[prow * NBINS + b];
            float m = v / fmaxf(c, 1.f);
            mean[b] = m; ssum += m;
        }
        ssum = fmaxf(ssum, 1e-12f);
        float ent = 0.f;
#pragma unroll
        for (int b = 0; b < NBINS; b++) {
            float pb = mean[b] / ssum;
            ent += pb * logf(fmaxf(pb, 1e-12f));
        }
        const float LOGN = logf((float)NBINS);
        float mi = (LOGN + ent) / LOGN;
        int a_ = ag * 5 + a;
        atomicAdd(&out[(bc * 10 + p_) * 10 + a_], 0.25f * mi);
    }
}

// -------------------- launch --------------------
extern "C" void kernel_launch(void* const* d_in, const int* in_sizes, int n_in,
                              void* d_out, int out_size) {
    const float* x = (const float*)d_in[0];
    const float* K = (const float*)d_in[1];
    if (n_in >= 2 && in_sizes[0] == NF * LK) {   // robust to metadata order
        const float* t = x; x = K; K = t;
    }
    tw_kernel<<<1, 512>>>();
    pad_kernel<<<NROWS, 256>>>(x);
    conv_kernel<<<dim3(NF, NROWS), 256>>>(K);
    hilbert_kernel<<<NROWS * 10, 256>>>();
    cudaMemsetAsync(d_out, 0, (size_t)out_size * sizeof(float));
    mi_kernel<<<dim3(2, 10, 128), 128>>>((float*)d_out);
}

// round 9
// speedup vs baseline: 1.2814x; 1.0091x over previous
#include <cuda_runtime.h>
#include <math.h>

#define TT 2048
#define NROWS 128
#define NF 20
#define LK 769
#define PADL 384
#define SIGP_LEN 2816   /* TT + 2*384 */
#define NBINS 18
#define PI_F 3.14159265358979f

typedef unsigned long long ull;

// -------------------- scratch (no allocs allowed) --------------------
__device__ float g_sigp[NROWS * SIGP_LEN];            // 1.44 MB
__device__ float g_filt[NROWS * NF * TT];             // 21 MB
__device__ unsigned char g_bin[NROWS * 10 * TT];      // 2.6 MB
__device__ float g_amp[NROWS * 10 * TT];              // 10.5 MB
__device__ int   g_cnt[NROWS * 10 * NBINS];
__device__ float g_twr[512], g_twi[512];

// -------------------- f32x2 helpers (FFMA2: 2 MACs per fma-pipe slot) ---------
__device__ __forceinline__ ull packf2(float lo, float hi) {
    ull r;
    asm("mov.b64 %0, {%1, %2};" : "=l"(r)
        : "r"(__float_as_uint(lo)), "r"(__float_as_uint(hi)));
    return r;
}
__device__ __forceinline__ void fma2(ull& d, ull a, ull b) {
    asm("fma.rn.f32x2 %0, %1, %2, %0;" : "+l"(d) : "l"(a), "l"(b));
}
__device__ __forceinline__ float lo32(ull v) { return __uint_as_float((unsigned)v); }
__device__ __forceinline__ float hi32(ull v) { return __uint_as_float((unsigned)(v >> 32)); }

// -------------------- 0) twiddle precompute --------------------
__global__ void tw_kernel() {
    int t = threadIdx.x;
    float ang = -2.f * PI_F * (float)t / 2048.f;
    g_twr[t] = cosf(ang);
    g_twi[t] = sinf(ang);
}

// -------------------- 1) reflect pad (effective pad 384/side) --------------------
__global__ void pad_kernel(const float* __restrict__ x) {
    int row = blockIdx.x;
    const float* xr = x + row * TT;
    float* o = g_sigp + row * SIGP_LEN;
    for (int j = threadIdx.x; j < SIGP_LEN; j += blockDim.x) {
        int i = j - PADL;
        int src = (i < 0) ? -i : ((i >= TT) ? (2 * TT - 2 - i) : i);
        o[j] = xr[src];
    }
}

// -------------------- 2) FIR conv, trimmed, packed-f32x2 sliding window --------
// Accumulator pairs A[p] = (o_{2p}, o_{2p+1}); even/odd-aligned packed windows:
// E[q] = (s[2q], s[2q+1]), O[q] = (s[2q+1], s[2q+2]). Tap 2m uses E[m+p],
// tap 2m+1 uses O[m+p]. 32 FFMA2 per 8-tap chunk (vs 64 FFMA).
__global__ __launch_bounds__(256) void conv_kernel(const float* __restrict__ Kf) {
    __shared__ __align__(16) float ssig[2832];
    __shared__ __align__(16) float sk[784];
    __shared__ int s_lo, s_hi;
    int f = blockIdx.x, row = blockIdx.y;
    int tid = threadIdx.x;

    for (int j = tid; j < 2832; j += 256)
        ssig[j] = (j < SIGP_LEN) ? g_sigp[row * SIGP_LEN + j] : 0.f;
    for (int j = tid; j < 784; j += 256)
        sk[j] = (j < LK) ? Kf[f * LK + j] : 0.f;
    if (tid == 0) { s_lo = LK; s_hi = 0; }
    __syncthreads();

    int llo = LK, lhi = 0;
    for (int j = tid; j < LK; j += 256)
        if (sk[j] != 0.f) { if (j < llo) llo = j; if (j > lhi) lhi = j; }
    atomicMin(&s_lo, llo);
    atomicMax(&s_hi, lhi);
    __syncthreads();

    int l0 = s_lo & ~7;
    int l1 = (s_hi + 8) & ~7;     // exclusive; zero taps are free

    int t0 = tid * 8;             // 8 consecutive outputs per thread
    ull A0 = 0, A1 = 0, A2 = 0, A3 = 0;

    ull E[8], O[7];
    float s7;
    {
        float4 va = *(const float4*)&ssig[t0 + l0];
        float4 vb = *(const float4*)&ssig[t0 + l0 + 4];
        E[0] = packf2(va.x, va.y); E[1] = packf2(va.z, va.w);
        E[2] = packf2(vb.x, vb.y); E[3] = packf2(vb.z, vb.w);
        O[0] = packf2(va.y, va.z); O[1] = packf2(va.w, vb.x);
        O[2] = packf2(vb.y, vb.z);
        s7 = vb.w;
    }
    for (int l = l0; l < l1; l += 8) {
        float4 vc = *(const float4*)&ssig[t0 + l + 8];
        float4 vd = *(const float4*)&ssig[t0 + l + 12];
        E[4] = packf2(vc.x, vc.y); E[5] = packf2(vc.z, vc.w);
        E[6] = packf2(vd.x, vd.y); E[7] = packf2(vd.z, vd.w);
        O[3] = packf2(s7, vc.x);
        O[4] = packf2(vc.y, vc.z); O[5] = packf2(vc.w, vd.x);
        O[6] = packf2(vd.y, vd.z);
#pragma unroll
        for (int m = 0; m < 4; m++) {
            float k0 = sk[l + 2 * m];
            ull kk0 = packf2(k0, k0);
            fma2(A0, E[m],     kk0);
            fma2(A1, E[m + 1], kk0);
            fma2(A2, E[m + 2], kk0);
            fma2(A3, E[m + 3], kk0);
            float k1v = sk[l + 2 * m + 1];
            ull kk1 = packf2(k1v, k1v);
            fma2(A0, O[m],     kk1);
            fma2(A1, O[m + 1], kk1);
            fma2(A2, O[m + 2], kk1);
            fma2(A3, O[m + 3], kk1);
        }
        E[0] = E[4]; E[1] = E[5]; E[2] = E[6]; E[3] = E[7];
        O[0] = O[4]; O[1] = O[5]; O[2] = O[6];
        s7 = vd.w;
    }
    float* o = &g_filt[(row * NF + f) * TT + t0];
    *(float4*)&o[0] = make_float4(lo32(A0), hi32(A0), lo32(A1), hi32(A1));
    *(float4*)&o[4] = make_float4(lo32(A2), hi32(A2), lo32(A3), hi32(A3));
}

// -------------------- 3) 2048-pt radix-8 Stockham, ping-pong, fused ------------
#define IDX(i) ((i) + ((i) >> 3))

// radix-8 butterfly core: x[8] -> y[8] (DIF order, outputs j=0..7)
__device__ __forceinline__ void bfly8(const float* xr, const float* xi,
                                      float* yr, float* yi) {
    const float C = 0.70710678118654752f;
    float a0r=xr[0]+xr[4], a0i=xi[0]+xi[4];
    float a1r=xr[0]-xr[4], a1i=xi[0]-xi[4];
    float a2r=xr[2]+xr[6], a2i=xi[2]+xi[6];
    float a3r=xr[2]-xr[6], a3i=xi[2]-xi[6];
    float a4r=xr[1]+xr[5], a4i=xi[1]+xi[5];
    float a5r=xr[1]-xr[5], a5i=xi[1]-xi[5];
    float a6r=xr[3]+xr[7], a6i=xi[3]+xi[7];
    float a7r=xr[3]-xr[7], a7i=xi[3]-xi[7];
    float t3r =  a3i, t3i = -a3r;          // -i * a3
    float t7r =  a7i, t7i = -a7r;          // -i * a7
    float b0r=a0r+a2r, b0i=a0i+a2i;
    float b1r=a0r-a2r, b1i=a0i-a2i;
    float b2r=a1r+t3r, b2i=a1i+t3i;
    float b3r=a1r-t3r, b3i=a1i-t3i;
    float b4r=a4r+a6r, b4i=a4i+a6i;
    float b5r=a4r-a6r, b5i=a4i-a6i;
    float b6r=a5r+t7r, b6i=a5i+t7i;
    float b7r=a5r-t7r, b7i=a5i-t7i;
    float o1r =  C*(b6r + b6i), o1i =  C*(b6i - b6r);   // w8^1 * b6
    float o3r =  C*(b7i - b7r), o3i = -C*(b7r + b7i);   // w8^3 * b7
    yr[0]=b0r+b4r; yi[0]=b0i+b4i;
    yr[4]=b0r-b4r; yi[4]=b0i-b4i;
    yr[1]=b2r+o1r; yi[1]=b2i+o1i;
    yr[5]=b2r-o1r; yi[5]=b2i-o1i;
    yr[2]=b1r+b5i; yi[2]=b1i-b5r;          // + (-i)*b5
    yr[6]=b1r-b5i; yi[6]=b1i+b5r;
    yr[3]=b3r+o3r; yi[3]=b3i+o3i;
    yr[7]=b3r-o3r; yi[7]=b3i-o3i;
}

// MODE 0: read smem. MODE 1: read global xs/ys (s==1). MODE 2: read smem with
// fused Hilbert multiplier W = conj(-i*sgn(k)*Z) (s==1).
template<int MODE>
__device__ __forceinline__ void stage8(
    const float* sr, const float* si,
    const float* __restrict__ gx, const float* __restrict__ gy,
    float* dr, float* di, int s, int tid,
    const float* twr, const float* twi)
{
    int b = tid;
    int k1 = b & ~(s - 1);
    int d  = b & (s - 1);
    int base = 8 * k1 + d;

    float xr[8], xi[8];
#pragma unroll
    for (int m = 0; m < 8; m++) {
        int k = b + m * 256;
        if (MODE == 1) { xr[m] = gx[k]; xi[m] = gy[k]; }
        else if (MODE == 0) { xr[m] = sr[IDX(k)]; xi[m] = si[IDX(k)]; }
        else {
            float sg = (k == 0 || k == 1024) ? 0.f : (k < 1024 ? 1.f : -1.f);
            float zr = sr[IDX(k)], zi = si[IDX(k)];
            xr[m] = sg * zi;  xi[m] = sg * zr;
        }
    }
    float yr[8], yi[8];
    bfly8(xr, xi, yr, yi);

    // twiddle powers, depth-3 product tree
    float w1r = twr[k1], w1i = twi[k1];
    float w2r = w1r*w1r - w1i*w1i, w2i = 2.f*w1r*w1i;
    float w4r = w2r*w2r - w2i*w2i, w4i = 2.f*w2r*w2i;
    float w3r = w2r*w1r - w2i*w1i, w3i = w2r*w1i + w2i*w1r;
    float w5r = w4r*w1r - w4i*w1i, w5i = w4r*w1i + w4i*w1r;
    float w6r = w3r*w3r - w3i*w3i, w6i = 2.f*w3r*w3i;
    float w7r = w4r*w3r - w4i*w3i, w7i = w4r*w3i + w4i*w3r;

    dr[IDX(base)]       = yr[0];                    di[IDX(base)]       = yi[0];
    dr[IDX(base + s)]   = yr[1]*w1r - yi[1]*w1i;    di[IDX(base + s)]   = yr[1]*w1i + yi[1]*w1r;
    dr[IDX(base + 2*s)] = yr[2]*w2r - yi[2]*w2i;    di[IDX(base + 2*s)] = yr[2]*w2i + yi[2]*w2r;
    dr[IDX(base + 3*s)] = yr[3]*w3r - yi[3]*w3i;    di[IDX(base + 3*s)] = yr[3]*w3i + yi[3]*w3r;
    dr[IDX(base + 4*s)] = yr[4]*w4r - yi[4]*w4i;    di[IDX(base + 4*s)] = yr[4]*w4i + yi[4]*w4r;
    dr[IDX(base + 5*s)] = yr[5]*w5r - yi[5]*w5i;    di[IDX(base + 5*s)] = yr[5]*w5i + yi[5]*w5r;
    dr[IDX(base + 6*s)] = yr[6]*w6r - yi[6]*w6i;    di[IDX(base + 6*s)] = yr[6]*w6i + yi[6]*w6r;
    dr[IDX(base + 7*s)] = yr[7]*w7r - yi[7]*w7i;    di[IDX(base + 7*s)] = yr[7]*w7i + yi[7]*w7r;
}

// final radix-4 stage (s=512, unit twiddles), smem -> smem
__device__ __forceinline__ void stage4_smem(const float* sr, const float* si,
                                            float* dr, float* di, int tid) {
#pragma unroll
    for (int u = 0; u < 2; u++) {
        int b = tid + u * 256;
        float r0 = sr[IDX(b)],        i0 = si[IDX(b)];
        float r1 = sr[IDX(b + 512)],  i1 = si[IDX(b + 512)];
        float r2 = sr[IDX(b + 1024)], i2 = si[IDX(b + 1024)];
        float r3 = sr[IDX(b + 1536)], i3 = si[IDX(b + 1536)];
        float apc_r = r0+r2, apc_i = i0+i2;
        float amc_r = r0-r2, amc_i = i0-i2;
        float bpd_r = r1+r3, bpd_i = i1+i3;
        float bmd_r = r1-r3, bmd_i = i1-i3;
        dr[IDX(b)]        = apc_r + bpd_r;  di[IDX(b)]        = apc_i + bpd_i;
        dr[IDX(b +  512)] = amc_r + bmd_i;  di[IDX(b +  512)] = amc_i - bmd_r;
        dr[IDX(b + 1024)] = apc_r - bpd_r;  di[IDX(b + 1024)] = apc_i - bpd_i;
        dr[IDX(b + 1536)] = amc_r - bmd_i;  di[IDX(b + 1536)] = amc_i + bmd_r;
    }
}

// Packed dual-signal Hilbert: z = x + i*y, fwd FFT (stage0 reads global),
// multiplier fused into inverse's stage0, epilogue fused into final r4.
__global__ __launch_bounds__(256) void hilbert_kernel() {
    __shared__ __align__(16) float Ar[2304], Ai[2304], Br[2304], Bi[2304];
    __shared__ float twr[256], twi[256];
    __shared__ int hist[NBINS];
    int tid = threadIdx.x;
    int pb = blockIdx.x;            // 0..1279
    int row = pb / 10, fp = pb % 10;

    twr[tid] = g_twr[tid];
    twi[tid] = g_twi[tid];
    if (tid < NBINS) hist[tid] = 0;

    const float* xs = &g_filt[(row * NF + fp) * TT];        // pha-band signal
    const float* ys = &g_filt[(row * NF + fp + 10) * TT];   // amp-band signal
    __syncthreads();

    // FFT1
    stage8<1>(0, 0, xs, ys, Ar, Ai, 1, tid, twr, twi);   __syncthreads();
    stage8<0>(Ar, Ai, 0, 0, Br, Bi, 8, tid, twr, twi);   __syncthreads();
    stage8<0>(Br, Bi, 0, 0, Ar, Ai, 64, tid, twr, twi);  __syncthreads();
    stage4_smem(Ar, Ai, Br, Bi, tid);                    __syncthreads();
    // FFT2 (multiplier fused into stage0 reads)
    stage8<2>(Br, Bi, 0, 0, Ar, Ai, 1, tid, twr, twi);   __syncthreads();
    stage8<0>(Ar, Ai, 0, 0, Br, Bi, 8, tid, twr, twi);   __syncthreads();
    stage8<0>(Br, Bi, 0, 0, Ar, Ai, 64, tid, twr, twi);  __syncthreads();

    // final r4 from Ar/Ai straight into the epilogue (no smem write)
    const float scale = 1.f / 2048.f;
    const float B_OVER_2PI = (float)NBINS / (2.f * PI_F);
    int orow = row * 10 + fp;
#pragma unroll
    for (int u = 0; u < 2; u++) {
        int b = tid + u * 256;
        float r0 = Ar[IDX(b)],        i0 = Ai[IDX(b)];
        float r1 = Ar[IDX(b + 512)],  i1 = Ai[IDX(b + 512)];
        float r2 = Ar[IDX(b + 1024)], i2 = Ai[IDX(b + 1024)];
        float r3 = Ar[IDX(b + 1536)], i3 = Ai[IDX(b + 1536)];
        float apc_r = r0+r2, apc_i = i0+i2;
        float amc_r = r0-r2, amc_i = i0-i2;
        float bpd_r = r1+r3, bpd_i = i1+i3;
        float bmd_r = r1-r3, bmd_i = i1-i3;
        float outr[4], outi[4];
        int   idx[4];
        outr[0] = apc_r + bpd_r;  outi[0] = apc_i + bpd_i;  idx[0] = b;
        outr[1] = amc_r + bmd_i;  outi[1] = amc_i - bmd_r;  idx[1] = b + 512;
        outr[2] = apc_r - bpd_r;  outi[2] = apc_i - bpd_i;  idx[2] = b + 1024;
        outr[3] = amc_r - bmd_i;  outi[3] = amc_i + bmd_r;  idx[3] = b + 1536;
#pragma unroll
        for (int q = 0; q < 4; q++) {
            int j = idx[q];
            float hx =  outr[q] * scale;
            float hy = -outi[q] * scale;
            float re = xs[j];
            float ph = atan2f(hx, re);
            int bin = (int)floorf((ph + PI_F) * B_OVER_2PI);
            bin = bin < 0 ? 0 : (bin > NBINS - 1 ? NBINS - 1 : bin);
            g_bin[orow * TT + j] = (unsigned char)bin;
            atomicAdd(&hist[bin], 1);
            float ay = ys[j];
            g_amp[orow * TT + j] = sqrtf(ay * ay + hy * hy);
        }
    }
    __syncthreads();
    if (tid < NBINS) g_cnt[orow * NBINS + tid] = hist[tid];
}

// -------------------- 4) modulation index v2 ----------------------------------
__global__ __launch_bounds__(128) void mi_kernel(float* __restrict__ out) {
    __shared__ float red[90 * 128];   // 46080 B
    int tid = threadIdx.x;
    int ag = blockIdx.x, p_ = blockIdx.y, z = blockIdx.z;
    int bc = z >> 2, sp = z & 3;
    int mp = p_ * 4 + sp;
    int prow = (bc * 4 + mp / 10) * 10 + (mp % 10);
    const unsigned char* bp = g_bin + prow * TT;

    const float* ap[5];
#pragma unroll
    for (int ai = 0; ai < 5; ai++) {
        int ma = (ag * 5 + ai) * 4 + sp;
        int arow = (bc * 4 + ma / 10) * 10 + (ma % 10);
        ap[ai] = g_amp + arow * TT;
    }

#pragma unroll
    for (int j = 0; j < 90; j++) red[j * 128 + tid] = 0.f;
    __syncthreads();

    int t0 = tid * 16;  // 16 contiguous samples per thread
#pragma unroll
    for (int c = 0; c < 4; c++) {
        uchar4 b4 = *(const uchar4*)(bp + t0 + c * 4);
        int i0 = (int)b4.x * 128 + tid;
        int i1 = (int)b4.y * 128 + tid;
        int i2 = (int)b4.z * 128 + tid;
        int i3 = (int)b4.w * 128 + tid;
#pragma unroll
        for (int ai = 0; ai < 5; ai++) {
            float4 v = *(const float4*)(ap[ai] + t0 + c * 4);
            int base = ai * (18 * 128);
            red[base + i0] += v.x;
            red[base + i1] += v.y;
            red[base + i2] += v.z;
            red[base + i3] += v.w;
        }
    }
    __syncthreads();

#pragma unroll
    for (int sh = 6; sh >= 0; sh--) {
        int s = 1 << sh;
        for (int k = tid; k < 90 * s; k += 128) {
            int j = k >> sh;
            int t = k & (s - 1);
            red[j * 128 + t] += red[j * 128 + t + s];
        }
        __syncthreads();
    }

    if (tid < 5) {
        int a = tid;
        float mean[NBINS];
        float ssum = 0.f;
#pragma unroll
        for (int b = 0; b < NBINS; b++) {
            float v = red[(a * 18 + b) * 128];
            float c = (float)g_cnt[prow * NBINS + b];
            float m = v / fmaxf(c, 1.f);
            mean[b] = m; ssum += m;
        }
        ssum = fmaxf(ssum, 1e-12f);
        float ent = 0.f;
#pragma unroll
        for (int b = 0; b < NBINS; b++) {
            float pb = mean[b] / ssum;
            ent += pb * logf(fmaxf(pb, 1e-12f));
        }
        const float LOGN = logf((float)NBINS);
        float mi = (LOGN + ent) / LOGN;
        int a_ = ag * 5 + a;
        atomicAdd(&out[(bc * 10 + p_) * 10 + a_], 0.25f * mi);
    }
}

// -------------------- launch --------------------
extern "C" void kernel_launch(void* const* d_in, const int* in_sizes, int n_in,
                              void* d_out, int out_size) {
    const float* x = (const float*)d_in[0];
    const float* K = (const float*)d_in[1];
    if (n_in >= 2 && in_sizes[0] == NF * LK) {   // robust to metadata order
        const float* t = x; x = K; K = t;
    }
    tw_kernel<<<1, 512>>>();
    pad_kernel<<<NROWS, 256>>>(x);
    conv_kernel<<<dim3(NF, NROWS), 256>>>(K);
    hilbert_kernel<<<NROWS * 10, 256>>>();
    cudaMemsetAsync(d_out, 0, (size_t)out_size * sizeof(float));
    mi_kernel<<<dim3(2, 10, 128), 128>>>((float*)d_out);
}